// round 13
// baseline (speedup 1.0000x reference)
#include <cuda_runtime.h>
#include <math.h>

#define T_  128
#define B_  32
#define I_  128
#define H_  128
#define R_  100
#define O_  64
#define RH_ (R_*H_)       // 12800
#define COLS_ (H_*B_)     // 4096 flat (k*32+b) columns per region

typedef unsigned long long u64;

// Scratch (static device globals)
static __device__ float g_inp[(size_t)T_*R_*B_*H_];   // [t][r][b][g]
static __device__ float g_P  [(size_t)R_*B_*H_];      // [r][b*128+g]
static __device__ float g_Hbr[(size_t)T_*B_*RH_];     // [t][b][r*128+g] (out)
static __device__ float g_Hkb[(size_t)T_*R_*COLS_];   // [t][r][k*32+b]
static __device__ float g_msg[(size_t)R_*COLS_];      // [j][k*32+b]

// ---- packed f32x2 helpers (sm_103a) ----
__device__ __forceinline__ u64 pk2(float lo, float hi){
    u64 r; asm("mov.b64 %0, {%1,%2};" : "=l"(r) : "f"(lo), "f"(hi)); return r;
}
__device__ __forceinline__ void up2(u64 v, float& lo, float& hi){
    asm("mov.b64 {%0,%1}, %2;" : "=f"(lo), "=f"(hi) : "l"(v));
}
__device__ __forceinline__ u64 fma2(u64 a, u64 b, u64 c){
    u64 d; asm("fma.rn.f32x2 %0, %1, %2, %3;" : "=l"(d) : "l"(a), "l"(b), "l"(c)); return d;
}
__device__ __forceinline__ float tanha(float x){
    float y; asm("tanh.approx.f32 %0, %1;" : "=f"(y) : "f"(x)); return y;
}

// ============================================================================
// inp_kernel (proven ~40% fma): inp[t,r,b,g] = bias[r,g] + sum_i x[t,b,i]*W_ih[r,i,g]
// grid (R_, T_), 256 thr.
// ============================================================================
__global__ __launch_bounds__(256) void inp_kernel(const float* __restrict__ x,
                                                  const float* __restrict__ W_ih,
                                                  const float* __restrict__ bias){
    int r = blockIdx.x, t = blockIdx.y;
    __shared__ u64 xs[16][128];
    const float* xt = x + (size_t)t*B_*I_;
    for (int idx = threadIdx.x; idx < B_*I_; idx += 256){
        int b = idx >> 7, k = idx & 127;
        reinterpret_cast<float*>(&xs[b>>1][k])[b&1] = xt[idx];
    }
    __syncthreads();

    int gg = threadIdx.x & 63, quad = threadIdx.x >> 6;
    float bva = bias[r*H_ + gg], bvb = bias[r*H_ + gg + 64];
    u64 acc[8];
#pragma unroll
    for (int p=0;p<4;p++){ acc[p*2+0] = pk2(bva,bva); acc[p*2+1] = pk2(bvb,bvb); }

    const float* W = W_ih + (size_t)r*I_*H_;
#pragma unroll 4
    for (int k=0;k<I_;k++){
        float wa = W[(size_t)k*H_ + gg];
        float wb = W[(size_t)k*H_ + gg + 64];
        u64 wad = pk2(wa,wa), wbd = pk2(wb,wb);
#pragma unroll
        for (int p=0;p<4;p++){
            u64 xv = xs[quad*4+p][k];
            acc[p*2+0] = fma2(xv, wad, acc[p*2+0]);
            acc[p*2+1] = fma2(xv, wbd, acc[p*2+1]);
        }
    }
    float* op = g_inp + (size_t)(t*R_ + r)*B_*H_;
#pragma unroll
    for (int p=0;p<4;p++){
        int b0 = quad*8 + 2*p;
#pragma unroll
        for (int e=0;e<2;e++){
            float lo, hi; up2(acc[p*2+e], lo, hi);
            op[b0*H_     + gg + e*64] = lo;
            op[(b0+1)*H_ + gg + e*64] = hi;
        }
    }
}

// ============================================================================
// K1: grid 528 x 128 thr, 40KB dyn smem.
//  blocks 0..399  : (r=bx>>2, gq=bx&3): P[r][:,32g] = inp[t,r] + H[t-1]@W_hh
//                   (W slice + h pairs in smem; inp via LDG)
//  blocks 400..527: msg 32-col strip = C^T H[t-1]  (C in smem, H via LDG)
// ============================================================================
#define K1_SMEM_FLOATS 10240   // 40 KB (region uses 8192)

__global__ __launch_bounds__(128) void k1_kernel(const float* __restrict__ W_hh,
                                                 const float* __restrict__ C,
                                                 int t){
    extern __shared__ float sm[];
    const int bx = blockIdx.x, tid = threadIdx.x;

    if (bx < 400){
        // -------------------- region block --------------------
        const int r  = bx >> 2;
        const int gq = bx & 3;
        const int bp = tid & 15, b0 = bp*2;
        const int gi = tid >> 4;
        const int g0 = gq*32 + gi*4;
        float*  sw = sm;                                    // [k*32+c] W_hh slice
        float2* sh = reinterpret_cast<float2*>(sm + 4096);  // [k*16+bp] h pairs

        u64 a0,a1,a2,a3;
        {
            const float* ip = g_inp + ((size_t)t*R_ + r)*B_*H_;
            ulonglong2 p0 = __ldcg(reinterpret_cast<const ulonglong2*>(ip + (size_t)b0*H_ + g0));
            ulonglong2 p1 = __ldcg(reinterpret_cast<const ulonglong2*>(ip + (size_t)(b0+1)*H_ + g0));
            a0=p0.x; a1=p0.y; a2=p1.x; a3=p1.y;
        }
        if (t > 0){
            const float4* ws = reinterpret_cast<const float4*>(W_hh + (size_t)r*H_*H_) + gq*8;
            float4* dw = reinterpret_cast<float4*>(sw);
#pragma unroll
            for (int it=0; it<8; it++){
                int q = tid + it*128;           // q = k*8 + c4
                dw[q] = __ldcg(ws + (size_t)(q>>3)*32 + (q&7));
            }
            const float4* hsrc = reinterpret_cast<const float4*>(
                g_Hkb + ((size_t)(t-1)*R_ + r)*COLS_);
            float4* dh = reinterpret_cast<float4*>(sh);
#pragma unroll
            for (int it=0; it<8; it++) dh[tid + it*128] = __ldcg(hsrc + tid + it*128);
            __syncthreads();

            const ulonglong2* wu = reinterpret_cast<const ulonglong2*>(sw);  // [k*8+gi]
#pragma unroll 4
            for (int k=0;k<H_;k++){
                ulonglong2 w = wu[k*8 + gi];
                float2 hp = sh[k*16 + bp];
                u64 h0 = pk2(hp.x,hp.x), h1 = pk2(hp.y,hp.y);
                a0 = fma2(w.x, h0, a0);  a1 = fma2(w.y, h0, a1);
                a2 = fma2(w.x, h1, a2);  a3 = fma2(w.y, h1, a3);
            }
        }
        ulonglong2 v0; v0.x=a0; v0.y=a1;
        ulonglong2 v1; v1.x=a2; v1.y=a3;
        *reinterpret_cast<ulonglong2*>(g_P + (size_t)r*4096 + (size_t)b0*H_ + g0)     = v0;
        *reinterpret_cast<ulonglong2*>(g_P + (size_t)r*4096 + (size_t)(b0+1)*H_ + g0) = v1;
    } else {
        // -------------------- msg block --------------------
        if (t == 0) return;
        float* Cs = sm;                      // 10000 floats
        const int m = bx - 400;              // 0..127
        const int col0 = m*32;
        {
            const float4* c4 = reinterpret_cast<const float4*>(C);
            float4* cd = reinterpret_cast<float4*>(Cs);
            for (int i=tid;i<2500;i+=128) cd[i] = __ldcg(c4 + i);
        }
        __syncthreads();

        const int col = tid & 31;
        const int jg  = tid >> 5;                          // 0..3 (warp id)
        const int njp = (jg < 2) ? 13 : 12;
        const int jp0 = (jg < 2) ? jg*13 : 26 + (jg-2)*12; // 50 pairs
        const int colg = col0 + col;

        u64 acc[13];
#pragma unroll
        for (int j=0;j<13;j++) acc[j] = 0ull;

        const float* Hb = g_Hkb + (size_t)(t-1)*R_*COLS_ + colg;
#pragma unroll 2
        for (int i=0;i<R_;i++){
            float h = __ldcg(Hb + (size_t)i*COLS_);        // coalesced across col
            u64 h2 = pk2(h, h);
            const u64* Cr = reinterpret_cast<const u64*>(Cs + i*R_ + jp0*2);
#pragma unroll
            for (int j=0;j<13;j++){
                if (j < njp) acc[j] = fma2(Cr[j], h2, acc[j]);
            }
        }
#pragma unroll
        for (int j=0;j<13;j++){
            if (j < njp){
                float lo, hi; up2(acc[j], lo, hi);
                int jj = (jp0 + j)*2;
                __stcg(&g_msg[(size_t)jj*COLS_     + colg], lo);
                __stcg(&g_msg[(size_t)(jj+1)*COLS_ + colg], hi);
            }
        }
    }
}

// ============================================================================
// K2: grid 400 x 128 thr, 32KB smem. (r,gq): H[t] slice = tanh(P + msg@W_rhh)
// ============================================================================
#define K2_SMEM_FLOATS 8192    // 32 KB

__global__ __launch_bounds__(128) void k2_kernel(const float* __restrict__ W_rhh,
                                                 int t){
    extern __shared__ float sm[];
    float*  sw  = sm;                                    // [k*32+c] W_rhh slice
    float2* sms = reinterpret_cast<float2*>(sm + 4096);  // [k*16+bp] msg pairs

    const int bx = blockIdx.x, tid = threadIdx.x;
    const int r  = bx >> 2;
    const int gq = bx & 3;
    const int bp = tid & 15, b0 = bp*2;
    const int gi = tid >> 4;
    const int g0 = gq*32 + gi*4;

    if (t > 0){
        const float4* ws = reinterpret_cast<const float4*>(W_rhh + (size_t)r*H_*H_) + gq*8;
        float4* dw = reinterpret_cast<float4*>(sw);
#pragma unroll
        for (int it=0; it<8; it++){
            int q = tid + it*128;
            dw[q] = __ldcg(ws + (size_t)(q>>3)*32 + (q&7));
        }
        const float4* msrc = reinterpret_cast<const float4*>(g_msg + (size_t)r*COLS_);
        float4* dm = reinterpret_cast<float4*>(sms);
#pragma unroll
        for (int it=0; it<8; it++) dm[tid + it*128] = __ldcg(msrc + tid + it*128);
        __syncthreads();
    }

    u64 a0,a1,a2,a3;
    {
        ulonglong2 p0 = *reinterpret_cast<const ulonglong2*>(
            g_P + (size_t)r*4096 + (size_t)b0*H_ + g0);
        ulonglong2 p1 = *reinterpret_cast<const ulonglong2*>(
            g_P + (size_t)r*4096 + (size_t)(b0+1)*H_ + g0);
        a0=p0.x; a1=p0.y; a2=p1.x; a3=p1.y;
    }
    if (t > 0){
        const ulonglong2* wu = reinterpret_cast<const ulonglong2*>(sw);
#pragma unroll 4
        for (int k=0;k<H_;k++){
            ulonglong2 w = wu[k*8 + gi];
            float2 mp = sms[k*16 + bp];
            u64 m0 = pk2(mp.x,mp.x), m1 = pk2(mp.y,mp.y);
            a0 = fma2(w.x, m0, a0);  a1 = fma2(w.y, m0, a1);
            a2 = fma2(w.x, m1, a2);  a3 = fma2(w.y, m1, a3);
        }
    }
    float d0,d1,d2,d3, e0,e1,e2,e3;
    up2(a0,d0,d1); up2(a1,d2,d3); up2(a2,e0,e1); up2(a3,e2,e3);
    d0=tanha(d0); d1=tanha(d1); d2=tanha(d2); d3=tanha(d3);
    e0=tanha(e0); e1=tanha(e1); e2=tanha(e2); e3=tanha(e3);

    float* Hbr = g_Hbr + (size_t)t*B_*RH_ + (size_t)r*H_;
    __stcg(reinterpret_cast<float4*>(Hbr + (size_t)b0*RH_ + g0),
           make_float4(d0,d1,d2,d3));
    __stcg(reinterpret_cast<float4*>(Hbr + (size_t)(b0+1)*RH_ + g0),
           make_float4(e0,e1,e2,e3));
    float* Hkb = g_Hkb + ((size_t)t*R_ + r)*COLS_;
    __stcg(reinterpret_cast<float2*>(Hkb + (g0+0)*32 + b0), make_float2(d0,e0));
    __stcg(reinterpret_cast<float2*>(Hkb + (g0+1)*32 + b0), make_float2(d1,e1));
    __stcg(reinterpret_cast<float2*>(Hkb + (g0+2)*32 + b0), make_float2(d2,e2));
    __stcg(reinterpret_cast<float2*>(Hkb + (g0+3)*32 + b0), make_float2(d3,e3));
}

// ============================================================================
// out[t,b,o] = H[t][b][:] @ W_out + b_out   grid (T,2), 128 thr
// ============================================================================
__global__ __launch_bounds__(128) void out_kernel(const float* __restrict__ W_out,
                                                  const float* __restrict__ b_out,
                                                  float* __restrict__ out){
    int t = blockIdx.x, bh = blockIdx.y;
    __shared__ u64 hsh[128][9];
    int tid = threadIdx.x;
    int og = tid & 15, rp = tid >> 4;
    int o0 = og*4;
    u64 acc[4];
    {
        const u64* bo = reinterpret_cast<const u64*>(b_out + o0);
        acc[0]=bo[0]; acc[1]=bo[1]; acc[2]=bo[0]; acc[3]=bo[1];
    }
    const float* Hb = g_Hbr + (size_t)t*B_*RH_ + (size_t)(bh*16)*RH_;
    for (int kt=0; kt<RH_/128; kt++){
        __syncthreads();
        for (int idx = tid; idx < 16*128; idx += 128){
            int b = idx >> 7, kk = idx & 127;
            reinterpret_cast<float*>(&hsh[kk][b>>1])[b&1] = Hb[(size_t)b*RH_ + kt*128 + kk];
        }
        __syncthreads();
#pragma unroll 4
        for (int kk=0; kk<128; kk++){
            int k = kt*128 + kk;
            ulonglong2 w = *reinterpret_cast<const ulonglong2*>(W_out + (size_t)k*O_ + o0);
            u64 hp = hsh[kk][rp];
            float h0, h1; up2(hp, h0, h1);
            u64 h0d = pk2(h0,h0), h1d = pk2(h1,h1);
            acc[0] = fma2(w.x, h0d, acc[0]);  acc[1] = fma2(w.y, h0d, acc[1]);
            acc[2] = fma2(w.x, h1d, acc[2]);  acc[3] = fma2(w.y, h1d, acc[3]);
        }
    }
    u64* op = reinterpret_cast<u64*>(out);
    int row0 = bh*16 + rp*2;
    size_t base0 = ((size_t)(t*B_ + row0  )*O_ + o0) >> 1;
    size_t base1 = ((size_t)(t*B_ + row0+1)*O_ + o0) >> 1;
    op[base0] = acc[0];  op[base0+1] = acc[1];
    op[base1] = acc[2];  op[base1+1] = acc[3];
}

// ============================================================================
// Launch: inp precompute (off critical path), 128 x (K1 -> K2), out.
// ============================================================================
extern "C" void kernel_launch(void* const* d_in, const int* in_sizes, int n_in,
                              void* d_out, int out_size){
    const float* x     = (const float*)d_in[0];
    const float* C     = (const float*)d_in[1];
    const float* W_ih  = (const float*)d_in[2];
    const float* W_hh  = (const float*)d_in[3];
    const float* W_rhh = (const float*)d_in[4];
    const float* bias  = (const float*)d_in[5];
    const float* W_out = (const float*)d_in[6];
    const float* b_out = (const float*)d_in[7];
    float* out = (float*)d_out;

    inp_kernel<<<dim3(R_, T_), 256>>>(x, W_ih, bias);

    for (int t = 0; t < T_; t++){
        k1_kernel<<<528, 128, K1_SMEM_FLOATS * sizeof(float)>>>(W_hh, C, t);
        k2_kernel<<<400, 128, K2_SMEM_FLOATS * sizeof(float)>>>(W_rhh, t);
    }

    out_kernel<<<dim3(T_, 2), 128>>>(W_out, b_out, out);
}

// round 14
// speedup vs baseline: 1.2528x; 1.2528x over previous
#include <cuda_runtime.h>
#include <math.h>

#define T_  128
#define B_  32
#define I_  128
#define H_  128
#define R_  100
#define O_  64
#define RH_ (R_*H_)       // 12800
#define COLS_ (H_*B_)     // 4096  (k*32+b) flat columns per region

typedef unsigned long long u64;

// Scratch (static device globals)
static __device__ float g_inp[(size_t)T_*R_*B_*H_];    // [T][R][b][g]
static __device__ float g_Hbr[(size_t)T_*B_*RH_];      // [T][b][r*H+g]  (for out_kernel)
static __device__ float g_Hkb[(size_t)T_*R_*COLS_];    // [T][r][g*32+b] (for phases)
static __device__ float g_msg[(size_t)R_*COLS_];       // [r][g*32+b]
static __device__ unsigned g_arrive;                   // grid-barrier counter

// ---- packed f32x2 helpers (sm_103a) ----
__device__ __forceinline__ u64 pk2(float lo, float hi){
    u64 r; asm("mov.b64 %0, {%1,%2};" : "=l"(r) : "f"(lo), "f"(hi)); return r;
}
__device__ __forceinline__ void up2(u64 v, float& lo, float& hi){
    asm("mov.b64 {%0,%1}, %2;" : "=f"(lo), "=f"(hi) : "l"(v));
}
__device__ __forceinline__ u64 fma2(u64 a, u64 b, u64 c){
    u64 d; asm("fma.rn.f32x2 %0, %1, %2, %3;" : "=l"(d) : "l"(a), "l"(b), "l"(c)); return d;
}
__device__ __forceinline__ float tanha(float x){
    float y; asm("tanh.approx.f32 %0, %1;" : "=f"(y) : "f"(x)); return y;
}

// ============================================================================
// Kernel 1: inp[t,r,b,g] = sum_i x[t,b,i]*W_ih[r,i,g] + bias[r,g]
// Also resets the grid-barrier counter.
// ============================================================================
__global__ __launch_bounds__(256) void inp_kernel(const float* __restrict__ x,
                                                  const float* __restrict__ W_ih,
                                                  const float* __restrict__ bias){
    if (blockIdx.x == 0 && blockIdx.y == 0 && threadIdx.x == 0) g_arrive = 0u;

    int r = blockIdx.x, t = blockIdx.y;
    __shared__ u64 xs[16][128];
    const float* xt = x + (size_t)t*B_*I_;
    for (int idx = threadIdx.x; idx < B_*I_; idx += 256){
        int b = idx >> 7, k = idx & 127;
        reinterpret_cast<float*>(&xs[b>>1][k])[b&1] = xt[idx];
    }
    __syncthreads();

    int gg = threadIdx.x & 63, quad = threadIdx.x >> 6;
    float bva = bias[r*H_ + gg], bvb = bias[r*H_ + gg + 64];
    u64 acc[8];
#pragma unroll
    for (int p=0;p<4;p++){ acc[p*2+0] = pk2(bva,bva); acc[p*2+1] = pk2(bvb,bvb); }

    const float* W = W_ih + (size_t)r*I_*H_;
#pragma unroll 4
    for (int k=0;k<I_;k++){
        float wa = W[(size_t)k*H_ + gg];
        float wb = W[(size_t)k*H_ + gg + 64];
        u64 wad = pk2(wa,wa), wbd = pk2(wb,wb);
#pragma unroll
        for (int p=0;p<4;p++){
            u64 xv = xs[quad*4+p][k];
            acc[p*2+0] = fma2(xv, wad, acc[p*2+0]);
            acc[p*2+1] = fma2(xv, wbd, acc[p*2+1]);
        }
    }
    float* op = g_inp + (size_t)(t*R_ + r)*B_*H_;
#pragma unroll
    for (int p=0;p<4;p++){
        int b0 = quad*8 + 2*p;
#pragma unroll
        for (int e=0;e<2;e++){
            float lo, hi; up2(acc[p*2+e], lo, hi);
            op[b0*H_     + gg + e*64] = lo;
            op[(b0+1)*H_ + gg + e*64] = hi;
        }
    }
}

// ============================================================================
// Persistent recurrent kernel (single launch): grid = 100, 512 threads.
// smem: W_hh[r] | W_rhh[r] | C | hT | mT   (Hs for msg overlays hT/mT)
// ============================================================================
#define SM_W1   0
#define SM_W2   16384
#define SM_C    32768
#define SM_HT   42768          // 4096 floats [k*32+b]
#define SM_MT   46864          // 4096 floats
#define SM_FLOATS 50960        // 203840 bytes

__device__ __forceinline__ void gbar(unsigned target){
    __threadfence();
    __syncthreads();
    if (threadIdx.x == 0){
        atomicAdd(&g_arrive, 1u);
        volatile unsigned* va = &g_arrive;
        while (*va < target) { }
    }
    __syncthreads();
}

// phase A body: NJP j-pairs, 2 cols (c, c+32) within the strip
template<int NJP>
__device__ __forceinline__ void msg_body(const float* __restrict__ Cs,
                                         const float* __restrict__ Hs,
                                         int c, int jp0, int col0){
    u64 acc[NJP*2];
#pragma unroll
    for (int j=0;j<NJP*2;j++) acc[j] = 0ull;
#pragma unroll 2
    for (int i=0;i<R_;i++){
        float h0 = Hs[i*64 + c], h1 = Hs[i*64 + c + 32];
        u64 h0d = pk2(h0,h0), h1d = pk2(h1,h1);
        const float* Cr = Cs + i*R_ + jp0*2;
#pragma unroll
        for (int j=0;j<NJP;j++){
            u64 Cv = *reinterpret_cast<const u64*>(Cr + 2*j);   // {C[i,j],C[i,j+1]}
            acc[j*2+0] = fma2(Cv, h0d, acc[j*2+0]);
            acc[j*2+1] = fma2(Cv, h1d, acc[j*2+1]);
        }
    }
#pragma unroll
    for (int j=0;j<NJP;j++){
        int jj = (jp0 + j)*2;
#pragma unroll
        for (int e=0;e<2;e++){
            float lo, hi; up2(acc[j*2+e], lo, hi);
            int col = col0 + c + e*32;
            __stcg(&g_msg[(size_t)jj*COLS_     + col], lo);
            __stcg(&g_msg[(size_t)(jj+1)*COLS_ + col], hi);
        }
    }
}

__global__ __launch_bounds__(512,1) void rnn_persist(const float* __restrict__ W_hh,
                                                     const float* __restrict__ W_rhh,
                                                     const float* __restrict__ C){
    extern __shared__ float sm[];
    float* w1 = sm + SM_W1;
    float* w2 = sm + SM_W2;
    float* Cs = sm + SM_C;
    float* hT = sm + SM_HT;
    float* mT = sm + SM_MT;
    float* Hs = hT;                       // phase-A overlay (6400 floats)

    const int r = blockIdx.x, tid = threadIdx.x;

    // stage region weights + connectome once
    {
        const float4* a  = reinterpret_cast<const float4*>(W_hh  + (size_t)r*H_*H_);
        const float4* bb = reinterpret_cast<const float4*>(W_rhh + (size_t)r*H_*H_);
        float4* d1 = reinterpret_cast<float4*>(w1);
        float4* d2 = reinterpret_cast<float4*>(w2);
        for (int i=tid;i<4096;i+=512){ d1[i]=a[i]; d2[i]=bb[i]; }
        const float4* c4 = reinterpret_cast<const float4*>(C);
        float4* dc = reinterpret_cast<float4*>(Cs);
        for (int i=tid;i<2500;i+=512) dc[i]=c4[i];
    }

    // phase-B mapping: gg -> g-cols {gg, gg+64}; bq -> b0..b0+3 (2 pairs)
    const int gg = tid & 63;
    const int bq = tid >> 6;
    const int b0 = bq*4;
    // phase-A mapping
    const int c  = tid & 31;
    const int jg = tid >> 5;
    const int jp0 = (jg<2)? jg*4 : 8 + (jg-2)*3;

    unsigned bars = 0;

    for (int t = 0; t < T_; t++){
        // ---------------- phase A: msg strips (blocks 0..63) ----------------
        if (t > 0){
            if (r < 64){
                const int col0 = r*64;
                const float* Hp = g_Hkb + (size_t)(t-1)*R_*COLS_ + col0;
                float4* Hs4 = reinterpret_cast<float4*>(Hs);
                for (int idx=tid; idx<1600; idx+=512){
                    int i = idx >> 4, c4i = idx & 15;
                    Hs4[idx] = __ldcg(reinterpret_cast<const float4*>(Hp + (size_t)i*COLS_) + c4i);
                }
                __syncthreads();
                if (jg < 2) msg_body<4>(Cs, Hs, c, jp0, col0);
                else        msg_body<3>(Cs, Hs, c, jp0, col0);
            }
            gbar(++bars * (unsigned)R_);
        }

        // ---------------- phase B ----------------
        u64 acc[4];
        {
            const float* ip = g_inp + ((size_t)t*R_ + r)*B_*H_;
#pragma unroll
            for (int pp=0;pp<2;pp++){
#pragma unroll
                for (int e=0;e<2;e++){
                    int g = gg + e*64, b = b0 + 2*pp;
                    acc[pp*2+e] = pk2(ip[b*H_ + g], ip[(b+1)*H_ + g]);
                }
            }
        }
        if (t > 0){
            const float4* Hp4 = reinterpret_cast<const float4*>(g_Hkb + ((size_t)(t-1)*R_ + r)*COLS_);
            const float4* Mp4 = reinterpret_cast<const float4*>(g_msg + (size_t)r*COLS_);
            float4* hT4 = reinterpret_cast<float4*>(hT);
            float4* mT4 = reinterpret_cast<float4*>(mT);
            for (int i=tid;i<1024;i+=512){ hT4[i] = __ldcg(Hp4+i); mT4[i] = __ldcg(Mp4+i); }
            __syncthreads();
#pragma unroll 4
            for (int k=0;k<H_;k++){
                float w1a = w1[k*H_ + gg], w1b = w1[k*H_ + gg + 64];
                float w2a = w2[k*H_ + gg], w2b = w2[k*H_ + gg + 64];
                u64 w1ad = pk2(w1a,w1a), w1bd = pk2(w1b,w1b);
                u64 w2ad = pk2(w2a,w2a), w2bd = pk2(w2b,w2b);
                ulonglong2 hA = *reinterpret_cast<const ulonglong2*>(hT + k*32 + b0);
                ulonglong2 mA = *reinterpret_cast<const ulonglong2*>(mT + k*32 + b0);
                acc[0] = fma2(hA.x, w1ad, acc[0]);  acc[0] = fma2(mA.x, w2ad, acc[0]);
                acc[1] = fma2(hA.x, w1bd, acc[1]);  acc[1] = fma2(mA.x, w2bd, acc[1]);
                acc[2] = fma2(hA.y, w1ad, acc[2]);  acc[2] = fma2(mA.y, w2ad, acc[2]);
                acc[3] = fma2(hA.y, w1bd, acc[3]);  acc[3] = fma2(mA.y, w2bd, acc[3]);
            }
            __syncthreads();   // hT/mT (and Hs overlay) free for next phase A
        }
        {
            float* Hbr = g_Hbr + (size_t)t*B_*RH_ + (size_t)r*H_;
            float* Hkb = g_Hkb + ((size_t)t*R_ + r)*COLS_;
#pragma unroll
            for (int pp=0;pp<2;pp++){
#pragma unroll
                for (int e=0;e<2;e++){
                    float lo, hi; up2(acc[pp*2+e], lo, hi);
                    float tl = tanha(lo), th = tanha(hi);
                    int g = gg + e*64, b = b0 + 2*pp;
                    __stcg(Hbr + (size_t)b*RH_     + g, tl);
                    __stcg(Hbr + (size_t)(b+1)*RH_ + g, th);
                    __stcg(reinterpret_cast<float2*>(Hkb + g*32 + b), make_float2(tl, th));
                }
            }
        }
        if (t < T_-1) gbar(++bars * (unsigned)R_);
    }
}

// ============================================================================
// Kernel 3: out[t,b,o] = H[t][b][:] @ W_out + b_out   grid (T,2), 128 thr
// ============================================================================
__global__ __launch_bounds__(128) void out_kernel(const float* __restrict__ W_out,
                                                  const float* __restrict__ b_out,
                                                  float* __restrict__ out){
    int t = blockIdx.x, bh = blockIdx.y;
    __shared__ u64 hsh[128][9];
    int tid = threadIdx.x;
    int og = tid & 15, rp = tid >> 4;
    int o0 = og*4;
    u64 acc[4];
    {
        const u64* bo = reinterpret_cast<const u64*>(b_out + o0);
        acc[0]=bo[0]; acc[1]=bo[1]; acc[2]=bo[0]; acc[3]=bo[1];
    }
    const float* Hb = g_Hbr + (size_t)t*B_*RH_ + (size_t)(bh*16)*RH_;
    for (int kt=0; kt<RH_/128; kt++){
        __syncthreads();
        for (int idx = tid; idx < 16*128; idx += 128){
            int b = idx >> 7, kk = idx & 127;
            reinterpret_cast<float*>(&hsh[kk][b>>1])[b&1] = Hb[(size_t)b*RH_ + kt*128 + kk];
        }
        __syncthreads();
#pragma unroll 4
        for (int kk=0; kk<128; kk++){
            int k = kt*128 + kk;
            ulonglong2 w = *reinterpret_cast<const ulonglong2*>(W_out + (size_t)k*O_ + o0);
            u64 hp = hsh[kk][rp];
            float h0, h1; up2(hp, h0, h1);
            u64 h0d = pk2(h0,h0), h1d = pk2(h1,h1);
            acc[0] = fma2(w.x, h0d, acc[0]);  acc[1] = fma2(w.y, h0d, acc[1]);
            acc[2] = fma2(w.x, h1d, acc[2]);  acc[3] = fma2(w.y, h1d, acc[3]);
        }
    }
    u64* op = reinterpret_cast<u64*>(out);
    int row0 = bh*16 + rp*2;
    size_t base0 = ((size_t)(t*B_ + row0  )*O_ + o0) >> 1;
    size_t base1 = ((size_t)(t*B_ + row0+1)*O_ + o0) >> 1;
    op[base0] = acc[0];  op[base0+1] = acc[1];
    op[base1] = acc[2];  op[base1+1] = acc[3];
}

// Profiling alignment pads (cheap no-ops so ncu -s 5 lands on rnn_persist).
__global__ void pad_kernel(){ }

// ============================================================================
// Launch: inp, 4x pad, rnn_persist (launch idx 5), out.
// ============================================================================
extern "C" void kernel_launch(void* const* d_in, const int* in_sizes, int n_in,
                              void* d_out, int out_size){
    const float* x     = (const float*)d_in[0];
    const float* C     = (const float*)d_in[1];
    const float* W_ih  = (const float*)d_in[2];
    const float* W_hh  = (const float*)d_in[3];
    const float* W_rhh = (const float*)d_in[4];
    const float* bias  = (const float*)d_in[5];
    const float* W_out = (const float*)d_in[6];
    const float* b_out = (const float*)d_in[7];
    float* out = (float*)d_out;

    cudaFuncSetAttribute(rnn_persist, cudaFuncAttributeMaxDynamicSharedMemorySize,
                         SM_FLOATS * (int)sizeof(float));

    inp_kernel<<<dim3(R_, T_), 256>>>(x, W_ih, bias);     // resets g_arrive
    pad_kernel<<<1, 32>>>();
    pad_kernel<<<1, 32>>>();
    pad_kernel<<<1, 32>>>();
    pad_kernel<<<1, 32>>>();
    rnn_persist<<<R_, 512, SM_FLOATS * sizeof(float)>>>(W_hh, W_rhh, C);
    out_kernel<<<dim3(T_, 2), 128>>>(W_out, b_out, out);
}